// round 2
// baseline (speedup 1.0000x reference)
#include <cuda_runtime.h>
#include <math.h>

#define Bq 32
#define Nn 256
#define WMw 64
#define Rr 4
#define Hh 512
#define Dd 512
#define Tt 128
#define IFACE 471
#define EPSf 1e-6f
#define G4H 2048   // 4*H
#define KIN 768    // D + R*WM

// -------- persistent state (device globals; no dynamic alloc) --------
__device__ float g_h[Bq*Hh];
__device__ float g_c[Bq*Hh];
__device__ float g_M[Bq*Nn*WMw];
__device__ float g_usage[Bq*Nn];
__device__ float g_rw[Bq*Rr*Nn];
__device__ float g_ww[Bq*Nn];
__device__ float g_prec[Bq*Nn];
__device__ float g_link[Bq*Nn*Nn];
__device__ float g_rvec[Bq*Rr*WMw];
__device__ float g_gpart[4*Bq*G4H];
__device__ float g_z[Bq*IFACE];
__device__ float g_outpre[Bq*Dd];
__device__ float g_invMn[Bq*Nn];
__device__ float g_wwsum[Bq];

__device__ __forceinline__ float sigm(float x){ return 1.f/(1.f+expf(-x)); }
__device__ __forceinline__ float softplusf(float x){ return fmaxf(x,0.f) + log1pf(expf(-fabsf(x))); }

// -------- init --------
__global__ void k_init(){
  int i = blockIdx.x*blockDim.x + threadIdx.x;
  int stride = gridDim.x*blockDim.x;
  for (int j=i; j<Bq*Nn*Nn; j+=stride) g_link[j]=0.f;
  for (int j=i; j<Bq*Nn*WMw; j+=stride) g_M[j]=EPSf;
  for (int j=i; j<Bq*Hh; j+=stride){ g_h[j]=0.f; g_c[j]=0.f; }
  for (int j=i; j<Bq*Nn; j+=stride){ g_usage[j]=0.f; g_ww[j]=0.f; g_prec[j]=0.f; }
  for (int j=i; j<Bq*Rr*Nn; j+=stride) g_rw[j]=0.f;
  for (int j=i; j<Bq*Rr*WMw; j+=stride) g_rvec[j]=0.f;
}

// -------- K1: gates GEMM (split-K=4, partials) --------
// grid (128, 4), block 128.  cols tile = 16, batch tiled in shared.
__global__ void k_gates(const float* __restrict__ emb,
                        const float* __restrict__ Wx,
                        const float* __restrict__ Wh, int t){
  const int col = blockIdx.x*16 + (threadIdx.x & 15);
  const int bg  = threadIdx.x >> 4;       // 0..7 -> batches bg*4..bg*4+3
  const int ks  = blockIdx.y;
  const int k0  = ks*320;
  __shared__ float xs[32][33];
  float acc0=0.f, acc1=0.f, acc2=0.f, acc3=0.f;

  for (int kk0=0; kk0<320; kk0+=32){
    const int kbase = k0 + kk0;
    // stage xin chunk [k 32][b 32]
    for (int i=threadIdx.x; i<1024; i+=128){
      int kk = i & 31, b = i >> 5;
      int k = kbase + kk;
      float v;
      if (k < Dd)        v = emb[((size_t)t*Bq + b)*Dd + k];
      else if (k < KIN)  v = g_rvec[b*Rr*WMw + (k - Dd)];
      else               v = g_h[b*Hh + (k - KIN)];
      xs[kk][b] = v;
    }
    __syncthreads();
    const float* wbase = (kbase < KIN) ? (Wx + (size_t)kbase*G4H)
                                       : (Wh + (size_t)(kbase-KIN)*G4H);
    #pragma unroll
    for (int kk=0; kk<32; kk++){
      float w = wbase[(size_t)kk*G4H + col];
      acc0 = fmaf(w, xs[kk][bg*4+0], acc0);
      acc1 = fmaf(w, xs[kk][bg*4+1], acc1);
      acc2 = fmaf(w, xs[kk][bg*4+2], acc2);
      acc3 = fmaf(w, xs[kk][bg*4+3], acc3);
    }
    __syncthreads();
  }
  float* gp = g_gpart + (size_t)ks*Bq*G4H;
  gp[(bg*4+0)*G4H + col] = acc0;
  gp[(bg*4+1)*G4H + col] = acc1;
  gp[(bg*4+2)*G4H + col] = acc2;
  gp[(bg*4+3)*G4H + col] = acc3;
}

// -------- K2: LSTM pointwise --------
__global__ void k_lstm(const float* __restrict__ b_lstm){
  int idx = blockIdx.x*256 + threadIdx.x;   // 0..16383
  int b = idx >> 9, j = idx & 511;
  float g4[4];
  #pragma unroll
  for (int g=0; g<4; g++){
    int col = g*Hh + j;
    float v = b_lstm[col];
    #pragma unroll
    for (int ks=0; ks<4; ks++) v += g_gpart[(size_t)ks*Bq*G4H + b*G4H + col];
    g4[g] = v;
  }
  float i_ = sigm(g4[0]), f_ = sigm(g4[1]), gg = tanhf(g4[2]), o_ = sigm(g4[3]);
  float c = f_*g_c[b*Hh+j] + i_*gg;
  g_c[b*Hh+j] = c;
  g_h[b*Hh+j] = o_*tanhf(c);
}

// -------- K3: z = h@W_iface + b ; out_pre = h@W_pre + b_pre --------
// grid 123, block 256.  col = bx*8 + tid&7 (0..982), b = tid>>3
__global__ void k_iface(const float* __restrict__ Wif, const float* __restrict__ bif,
                        const float* __restrict__ Wpre, const float* __restrict__ bpre){
  const int col = blockIdx.x*8 + (threadIdx.x & 7);
  const int b = threadIdx.x >> 3;
  const bool valid = (col < 983);
  const bool is_z = (col < IFACE);
  const float* wcol = valid ? (is_z ? (Wif + col) : (Wpre + (col - IFACE))) : Wif;
  const int wstride = is_z ? IFACE : Dd;
  __shared__ float hs[32][33];
  float acc = 0.f;
  for (int kk0=0; kk0<Hh; kk0+=32){
    for (int i=threadIdx.x; i<1024; i+=256){
      int kk = i & 31, bb = i >> 5;
      hs[kk][bb] = g_h[bb*Hh + kk0 + kk];
    }
    __syncthreads();
    if (valid){
      #pragma unroll
      for (int kk=0; kk<32; kk++)
        acc = fmaf(wcol[(size_t)(kk0+kk)*wstride], hs[kk][b], acc);
    }
    __syncthreads();
  }
  if (valid){
    if (is_z) g_z[b*IFACE + col] = acc + bif[col];
    else      g_outpre[b*Dd + (col - IFACE)] = acc + bpre[col - IFACE];
  }
}

// -------- K4: usage, allocation (stable sort), write content, ww --------
// grid 32 (batch), block 256 (n)
__global__ void k_memprep(){
  const int b = blockIdx.x, tid = threadIdx.x;
  const float* zb = g_z + b*IFACE;
  __shared__ float s_wk[WMw], s_red[Nn], s_u[Nn], s_alloc[Nn];
  __shared__ int s_idx[Nn];

  // usage update (uses OLD ww, OLD rw, current free gates)
  float ret = 1.f;
  #pragma unroll
  for (int r=0; r<Rr; r++){
    float fr = sigm(zb[453+r]);
    ret *= 1.f - fr * g_rw[(b*Rr+r)*Nn + tid];
  }
  float u = g_usage[b*Nn+tid], wo = g_ww[b*Nn+tid];
  u = (u + wo - u*wo)*ret;
  g_usage[b*Nn+tid] = u;

  // write content weights (OLD M)
  if (tid < WMw) s_wk[tid] = zb[260+tid];
  __syncthreads();
  float k2 = 0.f;
  #pragma unroll
  for (int w=0; w<WMw; w++) k2 += s_wk[w]*s_wk[w];
  float invk = 1.f/fmaxf(sqrtf(k2), EPSf);
  float wstr = 1.f + softplusf(zb[324]);
  const float* Mrow = g_M + ((size_t)b*Nn + tid)*WMw;
  float dot = 0.f, m2 = 0.f;
  #pragma unroll 8
  for (int w=0; w<WMw; w++){ float mv = Mrow[w]; dot = fmaf(mv, s_wk[w], dot); m2 = fmaf(mv, mv, m2); }
  float a = wstr * dot * invk / fmaxf(sqrtf(m2), EPSf);
  s_red[tid] = a; __syncthreads();
  for (int s=128; s>0; s>>=1){ if (tid<s) s_red[tid] = fmaxf(s_red[tid], s_red[tid+s]); __syncthreads(); }
  float mx = s_red[0]; __syncthreads();
  float e = expf(a - mx); s_red[tid] = e; __syncthreads();
  for (int s=128; s>0; s>>=1){ if (tid<s) s_red[tid] += s_red[tid+s]; __syncthreads(); }
  float cwn = e / s_red[0];
  __syncthreads();

  // stable ascending bitonic sort on (usage, idx)
  s_u[tid] = u; s_idx[tid] = tid; __syncthreads();
  for (int k=2; k<=Nn; k<<=1)
    for (int j=k>>1; j>0; j>>=1){
      int ixj = tid ^ j;
      if (ixj > tid){
        float ua = s_u[tid], ub = s_u[ixj];
        int ia = s_idx[tid], ib = s_idx[ixj];
        bool gt = (ua > ub) || (ua == ub && ia > ib);
        bool up = ((tid & k) == 0);
        if (gt == up){ s_u[tid]=ub; s_u[ixj]=ua; s_idx[tid]=ib; s_idx[ixj]=ia; }
      }
      __syncthreads();
    }

  // inclusive product scan -> exclusive
  s_red[tid] = s_u[tid]; __syncthreads();
  for (int off=1; off<Nn; off<<=1){
    float v = s_red[tid];
    if (tid >= off) v *= s_red[tid-off];
    __syncthreads();
    s_red[tid] = v; __syncthreads();
  }
  float excl = (tid > 0) ? s_red[tid-1] : 1.f;
  float asrt = (1.f - s_u[tid]) * excl;
  s_alloc[s_idx[tid]] = asrt;
  __syncthreads();

  // ww
  float ag = sigm(zb[457]), wg = sigm(zb[458]);
  float wwn = wg*(ag*s_alloc[tid] + (1.f-ag)*cwn);
  g_ww[b*Nn+tid] = wwn;
  s_red[tid] = wwn; __syncthreads();
  for (int s=128; s>0; s>>=1){ if (tid<s) s_red[tid] += s_red[tid+s]; __syncthreads(); }
  if (tid == 0) g_wwsum[b] = s_red[0];
}

// -------- K5: link update + M update + M row norms --------
// grid (32, 68), block 256.  y<64: link rows [4y,4y+4). y>=64: M rows [(y-64)*64, +64)
__global__ void k_write(){
  const int b = blockIdx.x, y = blockIdx.y, tid = threadIdx.x;
  __shared__ float s_ww[Nn];
  __shared__ float s_pr[Nn];
  __shared__ float s_ev[WMw], s_wv[WMw];
  s_ww[tid] = g_ww[b*Nn+tid];
  if (y < 64){
    s_pr[tid] = g_prec[b*Nn+tid];   // OLD precedence
    __syncthreads();
    float* Lb = g_link + (size_t)b*Nn*Nn;
    #pragma unroll
    for (int ii=0; ii<4; ii++){
      int i = y*4 + ii;
      float wi = s_ww[i];
      float v = (1.f - wi - s_ww[tid])*Lb[(size_t)i*Nn + tid] + wi*s_pr[tid];
      Lb[(size_t)i*Nn + tid] = (i == tid) ? 0.f : v;
    }
  } else {
    if (tid < WMw){ s_ev[tid] = sigm(g_z[b*IFACE + 325 + tid]); s_wv[tid] = g_z[b*IFACE + 389 + tid]; }
    __syncthreads();
    int base = (y - 64)*64;
    float* Mb = g_M + ((size_t)b*Nn + base)*WMw;
    #pragma unroll
    for (int k2=0; k2<16; k2++){
      int idx = tid + k2*256;
      int row = idx >> 6, w = idx & 63;
      float wwr = s_ww[base + row];
      float mv = Mb[idx];
      Mb[idx] = mv*(1.f - wwr*s_ev[w]) + wwr*s_wv[w];
    }
    __syncthreads();
    if (tid < 64){
      const float* Mr = Mb + tid*WMw;
      float s2 = 0.f;
      #pragma unroll 8
      for (int w=0; w<WMw; w++) s2 = fmaf(Mr[w], Mr[w], s2);
      g_invMn[b*Nn + base + tid] = 1.f/fmaxf(sqrtf(s2), EPSf);
    }
  }
}

// -------- K6: content read, fw/bw, rw combine, rvec, prec --------
// grid (32, 4), block 256
__global__ void k_read(){
  const int b = blockIdx.x, r = blockIdx.y, tid = threadIdx.x;
  __shared__ float s_rwo[Nn], s_key[WMw], s_fw[Nn], s_red[Nn], s_rwn[Nn];
  __shared__ float s_part[4][WMw];
  s_rwo[tid] = g_rw[(b*Rr+r)*Nn + tid];
  if (tid < WMw) s_key[tid] = g_z[b*IFACE + r*WMw + tid];
  __syncthreads();

  // content read
  float k2 = 0.f;
  #pragma unroll
  for (int w=0; w<WMw; w++) k2 += s_key[w]*s_key[w];
  float invk = 1.f/fmaxf(sqrtf(k2), EPSf);
  float beta = 1.f + softplusf(g_z[b*IFACE + 256 + r]);
  const float* Mrow = g_M + ((size_t)b*Nn + tid)*WMw;
  float dot = 0.f;
  #pragma unroll 8
  for (int w=0; w<WMw; w++) dot = fmaf(Mrow[w], s_key[w], dot);
  float a = beta * dot * invk * g_invMn[b*Nn + tid];
  s_red[tid] = a; __syncthreads();
  for (int s=128; s>0; s>>=1){ if (tid<s) s_red[tid] = fmaxf(s_red[tid], s_red[tid+s]); __syncthreads(); }
  float mx = s_red[0]; __syncthreads();
  float e = expf(a - mx); s_red[tid] = e; __syncthreads();
  for (int s=128; s>0; s>>=1){ if (tid<s) s_red[tid] += s_red[tid+s]; __syncthreads(); }
  float crn = e / s_red[0];
  __syncthreads();

  // bw (column access = coalesced)
  const float* Lb = g_link + (size_t)b*Nn*Nn;
  float bwn = 0.f;
  for (int j=0; j<Nn; j++) bwn = fmaf(Lb[(size_t)j*Nn + tid], s_rwo[j], bwn);

  // fw (warp-cooperative per row, coalesced)
  int lane = tid & 31, wid = tid >> 5;
  for (int m=0; m<32; m++){
    int n2 = wid*32 + m;
    const float* Lr = Lb + (size_t)n2*Nn;
    float p = 0.f;
    #pragma unroll
    for (int j=0; j<8; j++) p = fmaf(Lr[lane + j*32], s_rwo[lane + j*32], p);
    #pragma unroll
    for (int o=16; o>0; o>>=1) p += __shfl_down_sync(0xffffffffu, p, o);
    if (lane == 0) s_fw[n2] = p;
  }
  __syncthreads();

  // modes softmax + combine
  float z0 = g_z[b*IFACE + 459 + 3*r], z1 = g_z[b*IFACE + 460 + 3*r], z2 = g_z[b*IFACE + 461 + 3*r];
  float mm = fmaxf(z0, fmaxf(z1, z2));
  float e0 = expf(z0-mm), e1 = expf(z1-mm), e2 = expf(z2-mm);
  float inv = 1.f/(e0+e1+e2);
  float rwn = (e0*bwn + e1*crn + e2*s_fw[tid])*inv;
  g_rw[(b*Rr+r)*Nn + tid] = rwn;
  s_rwn[tid] = rwn;
  __syncthreads();

  // rvec = rw @ M
  int w = tid & 63, q = tid >> 6;
  float p = 0.f;
  for (int n=q*64; n<q*64+64; n++) p = fmaf(s_rwn[n], g_M[((size_t)b*Nn + n)*WMw + w], p);
  s_part[q][w] = p;
  __syncthreads();
  if (tid < WMw)
    g_rvec[(b*Rr+r)*WMw + tid] = s_part[0][tid] + s_part[1][tid] + s_part[2][tid] + s_part[3][tid];

  // prec update (once per batch; link update already consumed old prec in K5)
  if (r == 0){
    float pn = (1.f - g_wwsum[b])*g_prec[b*Nn + tid] + g_ww[b*Nn + tid];
    g_prec[b*Nn + tid] = pn;
  }
}

// -------- K7: out = out_pre + rvec_flat @ W_rout --------
// grid (32, 2), block 256
__global__ void k_out(const float* __restrict__ Wrout, float* __restrict__ out, int t){
  const int b = blockIdx.x;
  const int col = blockIdx.y*256 + threadIdx.x;
  __shared__ float rv[Nn];
  rv[threadIdx.x] = g_rvec[b*Rr*WMw + threadIdx.x];
  __syncthreads();
  float acc = g_outpre[b*Dd + col];
  #pragma unroll 8
  for (int k=0; k<Nn; k++) acc = fmaf(rv[k], Wrout[(size_t)k*Dd + col], acc);
  out[((size_t)t*Bq + b)*Dd + col] = acc;
}

// -------- launch --------
extern "C" void kernel_launch(void* const* d_in, const int* in_sizes, int n_in,
                              void* d_out, int out_size){
  const float* emb   = (const float*)d_in[0];
  const float* Wx    = (const float*)d_in[1];
  const float* Wh    = (const float*)d_in[2];
  const float* bl    = (const float*)d_in[3];
  const float* Wpre  = (const float*)d_in[4];
  const float* bpre  = (const float*)d_in[5];
  const float* Wif   = (const float*)d_in[6];
  const float* bif   = (const float*)d_in[7];
  const float* Wrout = (const float*)d_in[8];
  float* out = (float*)d_out;

  k_init<<<2048, 256>>>();
  for (int t=0; t<Tt; t++){
    k_gates<<<dim3(128,4), 128>>>(emb, Wx, Wh, t);
    k_lstm<<<64, 256>>>(bl);
    k_iface<<<123, 256>>>(Wif, bif, Wpre, bpre);
    k_memprep<<<32, 256>>>();
    k_write<<<dim3(32,68), 256>>>();
    k_read<<<dim3(32,4), 256>>>();
    k_out<<<dim3(32,2), 256>>>(Wrout, out, t);
  }
}